// round 8
// baseline (speedup 1.0000x reference)
#include <cuda_runtime.h>
#include <stdint.h>
#include <math.h>

#define NB        50
#define NF_DIST   1225          // 50*49/2
#define NF_ANG    48
#define NF_DIH    47
#define NFEAT     (NF_DIST + NF_ANG + 2*NF_DIH)   // 1367

#define OFF_ANG   NF_DIST                 // 1225
#define OFF_DCOS  (NF_DIST + NF_ANG)      // 1273
#define OFF_DSIN  (OFF_DCOS + NF_DIH)     // 1320

// 7 groups of 7 rows: inc0 = 7g+1, tasks per group = 50 - inc0. Total 196.
#define NTASK     196
#define T_ANG0    196
#define T_DIH0    (T_ANG0 + NF_ANG)       // 244
#define T_END     (T_DIH0 + NF_DIH)       // 291
#define NTHREADS  320

// Task: thread owns bead i, sweeps rows inc0..inc0+6.
// Packed: i (bits 0-5) | inc0 (bits 6-11) | f0 = C(inc0-1) (bits 12+).
struct TaskTable { uint32_t v[NTASK]; };
constexpr TaskTable make_tasks() {
    TaskTable t{};
    int n = 0;
    for (int g = 0; g < 7; ++g) {
        const int inc0 = 7 * g + 1;
        const int f0   = (inc0 - 1) * (100 - inc0) / 2;
        for (int i = 0; i < NB - inc0; ++i)
            t.v[n++] = (uint32_t)(i | (inc0 << 6) | (f0 << 12));
    }
    return t;
}
__device__ constexpr TaskTable g_tasks = make_tasks();

__device__ __forceinline__ float fast_sqrt(float x) {
    float r;
    asm("sqrt.approx.f32 %0, %1;" : "=f"(r) : "f"(x));
    return r;
}

__global__ __launch_bounds__(NTHREADS)
void protein_feat_kernel(const float* __restrict__ data,
                         float* __restrict__ out,
                         int n_frames)
{
    // Per-frame SoA: xy packed as float2 (LDS.64), z separate (LDS.32).
    __shared__ float2 sxy[2][NB];
    __shared__ float  sz [2][NB];

    const int tid    = threadIdx.x;
    const int frame0 = blockIdx.x * 2;
    const bool has2  = (frame0 + 1) < n_frames;

    // ---- stage up to 2 frames (300 floats, coalesced) ----
    const float* p = data + (size_t)frame0 * NB * 3;
    const int nstage = has2 ? 300 : 150;
    if (tid < nstage) {
        const float v  = p[tid];
        const int  fr  = tid / 150;
        const int  r   = tid - fr * 150;
        const int  bd  = r / 3;
        const int  c   = r - 3 * bd;
        if (c == 2) sz[fr][bd] = v;
        else        ((float*)&sxy[fr][bd])[c] = v;
    }
    __syncthreads();

    float* o0 = out + (size_t)frame0 * NFEAT;
    float* o1 = o0 + NFEAT;

    if (tid < NTASK) {
        // ---- distances: pair (i, j) for both frames ----
        const uint32_t tv = g_tasks.v[tid];
        const int i       = tv & 63;
        const int inc0    = (tv >> 6) & 63;
        const int rl      = NB - inc0;
        int f             = (int)(tv >> 12) + i;
        int j             = i + inc0;

        const float2 a0 = sxy[0][i]; const float a0z = sz[0][i];
        const float2 a1 = sxy[1][i]; const float a1z = sz[1][i];

        #pragma unroll
        for (int k = 0; k < 7; ++k) {
            if (j < NB) {
                const float2 b0 = sxy[0][j]; const float b0z = sz[0][j];
                const float2 b1 = sxy[1][j]; const float b1z = sz[1][j];

                const float dx0 = b0.x - a0.x;
                const float dy0 = b0.y - a0.y;
                const float dz0 = b0z  - a0z;
                const float dx1 = b1.x - a1.x;
                const float dy1 = b1.y - a1.y;
                const float dz1 = b1z  - a1z;

                const float s0 = fmaf(dx0, dx0, fmaf(dy0, dy0, dz0 * dz0));
                const float s1 = fmaf(dx1, dx1, fmaf(dy1, dy1, dz1 * dz1));

                o0[f] = fast_sqrt(s0);
                if (has2) o1[f] = fast_sqrt(s1);
            }
            f += rl - k;
            ++j;
        }
    }
    else if (tid < T_DIH0) {
        // ---- angles, both frames ----
        const int a = tid - T_ANG0;
        #pragma unroll
        for (int fr = 0; fr < 2; ++fr) {
            if (fr == 1 && !has2) break;
            const float2 P0 = sxy[fr][a];     const float P0z = sz[fr][a];
            const float2 P1 = sxy[fr][a + 1]; const float P1z = sz[fr][a + 1];
            const float2 P2 = sxy[fr][a + 2]; const float P2z = sz[fr][a + 2];

            const float b1x = P0.x - P1.x, b1y = P0.y - P1.y, b1z = P0z - P1z;
            const float b2x = P2.x - P1.x, b2y = P2.y - P1.y, b2z = P2z - P1z;

            const float dot = fmaf(b1x, b2x, fmaf(b1y, b2y, b1z * b2z));
            const float n1  = fmaf(b1x, b1x, fmaf(b1y, b1y, b1z * b1z));
            const float n2  = fmaf(b2x, b2x, fmaf(b2y, b2y, b2z * b2z));
            float ct = dot * rsqrtf(n1 * n2);
            ct = fminf(1.0f, fmaxf(-1.0f, ct));
            (fr ? o1 : o0)[OFF_ANG + a] = acosf(ct);
        }
    }
    else if (tid < T_END) {
        // ---- dihedrals (cos+sin fused), both frames ----
        const int d = tid - T_DIH0;
        #pragma unroll
        for (int fr = 0; fr < 2; ++fr) {
            if (fr == 1 && !has2) break;
            const float2 P0 = sxy[fr][d];     const float P0z = sz[fr][d];
            const float2 P1 = sxy[fr][d + 1]; const float P1z = sz[fr][d + 1];
            const float2 P2 = sxy[fr][d + 2]; const float P2z = sz[fr][d + 2];
            const float2 P3 = sxy[fr][d + 3]; const float P3z = sz[fr][d + 3];

            const float ax = P1.x - P0.x, ay = P1.y - P0.y, az = P1z - P0z;
            const float bx = P2.x - P1.x, by = P2.y - P1.y, bz = P2z - P1z;
            const float cx = P3.x - P2.x, cy = P3.y - P2.y, cz = P3z - P2z;

            const float p1x = ay * bz - az * by;
            const float p1y = az * bx - ax * bz;
            const float p1z = ax * by - ay * bx;
            const float p2x = by * cz - bz * cy;
            const float p2y = bz * cx - bx * cz;
            const float p2z = bx * cy - by * cx;

            const float n1sq  = fmaf(p1x, p1x, fmaf(p1y, p1y, p1z * p1z));
            const float n2sq  = fmaf(p2x, p2x, fmaf(p2y, p2y, p2z * p2z));
            const float inv12 = rsqrtf(n1sq * n2sq);

            float* oo = fr ? o1 : o0;
            const float dp = fmaf(p1x, p2x, fmaf(p1y, p2y, p1z * p2z));
            oo[OFF_DCOS + d] = dp * inv12;

            const float qx = p1y * p2z - p1z * p2y;
            const float qy = p1z * p2x - p1x * p2z;
            const float qz = p1x * p2y - p1y * p2x;
            const float num  = fmaf(qx, bx, fmaf(qy, by, qz * bz));
            const float bnsq = fmaf(bx, bx, fmaf(by, by, bz * bz));
            oo[OFF_DSIN + d] = num * inv12 * rsqrtf(bnsq);
        }
    }
}

extern "C" void kernel_launch(void* const* d_in, const int* in_sizes, int n_in,
                              void* d_out, int out_size)
{
    const float* data = (const float*)d_in[0];
    float* out = (float*)d_out;
    const int n_frames = in_sizes[0] / (NB * 3);
    const int n_blocks = (n_frames + 1) / 2;

    protein_feat_kernel<<<n_blocks, NTHREADS>>>(data, out, n_frames);
}

// round 9
// speedup vs baseline: 1.5953x; 1.5953x over previous
#include <cuda_runtime.h>
#include <stdint.h>
#include <math.h>

#define NB        50
#define NF_DIST   1225
#define NF_ANG    48
#define NF_DIH    47
#define NFEAT     (NF_DIST + NF_ANG + 2*NF_DIH)   // 1367

#define OFF_ANG   NF_DIST                 // 1225
#define OFF_DCOS  (NF_DIST + NF_ANG)      // 1273
#define OFF_DSIN  (OFF_DCOS + NF_DIH)     // 1320

// 7 groups of 7 rows: inc0 = 7g+1, tasks per group = 50 - inc0. Total 196.
#define NTASK     196
#define T_ANG0    196
#define T_DIH0    (T_ANG0 + NF_ANG)       // 244
#define T_END     (T_DIH0 + NF_DIH)       // 291
#define NTHREADS  320

struct TaskTable { uint32_t v[NTASK]; };
constexpr TaskTable make_tasks() {
    TaskTable t{};
    int n = 0;
    for (int g = 0; g < 7; ++g) {
        const int inc0 = 7 * g + 1;
        const int f0   = (inc0 - 1) * (100 - inc0) / 2;
        for (int i = 0; i < NB - inc0; ++i)
            t.v[n++] = (uint32_t)(i | (inc0 << 6) | (f0 << 12));
    }
    return t;
}
__device__ constexpr TaskTable g_tasks = make_tasks();

// ---- packed f32x2 helpers (sm_103a) ----
typedef unsigned long long u64;
__device__ __forceinline__ u64 f2_pack(float lo, float hi) {
    u64 r; asm("mov.b64 %0, {%1, %2};" : "=l"(r) : "f"(lo), "f"(hi)); return r;
}
__device__ __forceinline__ void f2_unpack(float& lo, float& hi, u64 v) {
    asm("mov.b64 {%0, %1}, %2;" : "=f"(lo), "=f"(hi) : "l"(v));
}
__device__ __forceinline__ u64 f2_add(u64 a, u64 b) {
    u64 r; asm("add.rn.f32x2 %0, %1, %2;" : "=l"(r) : "l"(a), "l"(b)); return r;
}
__device__ __forceinline__ u64 f2_mul(u64 a, u64 b) {
    u64 r; asm("mul.rn.f32x2 %0, %1, %2;" : "=l"(r) : "l"(a), "l"(b)); return r;
}
__device__ __forceinline__ u64 f2_fma(u64 a, u64 b, u64 c) {
    u64 r; asm("fma.rn.f32x2 %0, %1, %2, %3;" : "=l"(r) : "l"(a), "l"(b), "l"(c)); return r;
}
__device__ __forceinline__ float fast_sqrt(float x) {
    float r; asm("sqrt.approx.f32 %0, %1;" : "=f"(r) : "f"(x)); return r;
}

__global__ __launch_bounds__(NTHREADS)
void protein_feat_kernel(const float* __restrict__ data,
                         float* __restrict__ out,
                         int n_frames)
{
    // Coord-major, frame-interleaved: sX[b] = {x_frame0, x_frame1}
    __shared__ float2 sX[NB], sY[NB], sZ[NB];

    const int tid    = threadIdx.x;
    const int frame0 = blockIdx.x * 2;
    const int frame1 = (frame0 + 1 < n_frames) ? frame0 + 1 : frame0; // clamp

    // ---- stage both frames ----
    if (tid < 300) {
        const int fr = (tid >= 150);
        const int r  = tid - 150 * fr;
        const int bd = r / 3;
        const int c  = r - 3 * bd;
        const float v = data[(size_t)(fr ? frame1 : frame0) * (NB * 3) + r];
        float* dst = (c == 0) ? (float*)sX : (c == 1) ? (float*)sY : (float*)sZ;
        dst[2 * bd + fr] = v;
    }
    __syncthreads();

    float* o0 = out + (size_t)frame0 * NFEAT;
    const int o1off = (int)((frame1 - frame0) * NFEAT);   // NFEAT or 0

    if (tid < NTASK) {
        const uint32_t tv = g_tasks.v[tid];
        const int i       = tv & 63;
        const int inc0    = (tv >> 6) & 63;
        const int rl      = NB - inc0;
        int f             = (int)(tv >> 12) + i;
        int j             = i + inc0;

        // negated A bead, packed (both frames)
        const float2 Ax = sX[i], Ay = sY[i], Az = sZ[i];
        const u64 nax = f2_pack(-Ax.x, -Ax.y);
        const u64 nay = f2_pack(-Ay.x, -Ay.y);
        const u64 naz = f2_pack(-Az.x, -Az.y);

        #pragma unroll
        for (int k = 0; k < 7; ++k) {
            if (j < NB) {
                const u64 bx = *reinterpret_cast<const u64*>(&sX[j]);
                const u64 by = *reinterpret_cast<const u64*>(&sY[j]);
                const u64 bz = *reinterpret_cast<const u64*>(&sZ[j]);

                const u64 dx = f2_add(bx, nax);
                const u64 dy = f2_add(by, nay);
                const u64 dz = f2_add(bz, naz);

                const u64 s2 = f2_fma(dx, dx, f2_fma(dy, dy, f2_mul(dz, dz)));
                float s0, s1; f2_unpack(s0, s1, s2);

                float* po = o0 + f;
                po[0]     = fast_sqrt(s0);
                po[o1off] = fast_sqrt(s1);   // same value if clamped
            }
            f += rl - k;
            ++j;
        }
    }
    else if (tid < T_DIH0) {
        // ---- angles, both frames (scalar) ----
        const int a = tid - T_ANG0;
        const float* fx = (const float*)sX;
        const float* fy = (const float*)sY;
        const float* fz = (const float*)sZ;
        #pragma unroll
        for (int fr = 0; fr < 2; ++fr) {
            const int a0 = 2 * a + fr, a1 = a0 + 2, a2 = a0 + 4;
            const float b1x = fx[a0] - fx[a1];
            const float b1y = fy[a0] - fy[a1];
            const float b1z = fz[a0] - fz[a1];
            const float b2x = fx[a2] - fx[a1];
            const float b2y = fy[a2] - fy[a1];
            const float b2z = fz[a2] - fz[a1];

            const float dot = fmaf(b1x, b2x, fmaf(b1y, b2y, b1z * b2z));
            const float n1  = fmaf(b1x, b1x, fmaf(b1y, b1y, b1z * b1z));
            const float n2  = fmaf(b2x, b2x, fmaf(b2y, b2y, b2z * b2z));
            float ct = dot * rsqrtf(n1 * n2);
            ct = fminf(1.0f, fmaxf(-1.0f, ct));
            o0[fr * o1off + OFF_ANG + a] = acosf(ct);
        }
    }
    else if (tid < T_END) {
        // ---- dihedrals (cos+sin fused), both frames (scalar) ----
        const int d = tid - T_DIH0;
        const float* fx = (const float*)sX;
        const float* fy = (const float*)sY;
        const float* fz = (const float*)sZ;
        #pragma unroll
        for (int fr = 0; fr < 2; ++fr) {
            const int d0 = 2 * d + fr, d1 = d0 + 2, d2 = d0 + 4, d3 = d0 + 6;

            const float ax = fx[d1] - fx[d0], ay = fy[d1] - fy[d0], az = fz[d1] - fz[d0];
            const float bx = fx[d2] - fx[d1], by = fy[d2] - fy[d1], bz = fz[d2] - fz[d1];
            const float cx = fx[d3] - fx[d2], cy = fy[d3] - fy[d2], cz = fz[d3] - fz[d2];

            const float p1x = ay * bz - az * by;
            const float p1y = az * bx - ax * bz;
            const float p1z = ax * by - ay * bx;
            const float p2x = by * cz - bz * cy;
            const float p2y = bz * cx - bx * cz;
            const float p2z = bx * cy - by * cx;

            const float n1sq  = fmaf(p1x, p1x, fmaf(p1y, p1y, p1z * p1z));
            const float n2sq  = fmaf(p2x, p2x, fmaf(p2y, p2y, p2z * p2z));
            const float inv12 = rsqrtf(n1sq * n2sq);

            float* oo = o0 + fr * o1off;
            const float dp = fmaf(p1x, p2x, fmaf(p1y, p2y, p1z * p2z));
            oo[OFF_DCOS + d] = dp * inv12;

            const float qx = p1y * p2z - p1z * p2y;
            const float qy = p1z * p2x - p1x * p2z;
            const float qz = p1x * p2y - p1y * p2x;
            const float num  = fmaf(qx, bx, fmaf(qy, by, qz * bz));
            const float bnsq = fmaf(bx, bx, fmaf(by, by, bz * bz));
            oo[OFF_DSIN + d] = num * inv12 * rsqrtf(bnsq);
        }
    }
}

extern "C" void kernel_launch(void* const* d_in, const int* in_sizes, int n_in,
                              void* d_out, int out_size)
{
    const float* data = (const float*)d_in[0];
    float* out = (float*)d_out;
    const int n_frames = in_sizes[0] / (NB * 3);
    const int n_blocks = (n_frames + 1) / 2;

    protein_feat_kernel<<<n_blocks, NTHREADS>>>(data, out, n_frames);
}